// round 2
// baseline (speedup 1.0000x reference)
#include <cuda_runtime.h>

// Problem constants
#define T_  64
#define B_  128
#define N_  1024
#define TB  8192          // T_*B_
#define BN_ (B_*N_)       // 131072
#define VTH 1.0f
#define EPS 1e-5f

// -------- scratch (no allocation allowed -> __device__ globals) --------
__device__ float d_h1[TB * N_];            // 32 MB  linear1 output [tb, m]
__device__ float d_h2[TB * N_];            // 32 MB  linear2 output [tb, m]
__device__ float d_psum[2 * 32 * N_];      // BN stage-1 partial sums [mat][chunk][col]
__device__ float d_psq [2 * 32 * N_];      // BN stage-1 partial sum-of-squares
__device__ float d_scale[2 * N_];          // gamma * rsqrt(var+eps)
__device__ float d_bias [2 * N_];          // beta - mean*scale
__device__ float d_ssum[T_ * B_];          // spatial_sum [t,b]
__device__ float d_tsum[B_ * N_];          // temporal_sum [b,m]

// ======================= GEMM: H = X @ W^T ============================
// X: [TB, N_] row-major; W: [N_, N_] row-major (both K-major).
// H[tb, m] = sum_k X[tb,k] * W[m,k]
#define BM 128
#define BNT 128
#define BK 16
#define TM 8
#define TN 8

__global__ __launch_bounds__(256) void gemm_kernel(
    const float* __restrict__ X,
    const float* __restrict__ W1,
    const float* __restrict__ W2)
{
    const float* __restrict__ W = (blockIdx.z == 0) ? W1 : W2;
    float* __restrict__ H = (blockIdx.z == 0) ? d_h1 : d_h2;

    __shared__ float As[BK][BM];
    __shared__ float Bs[BK][BNT];

    const int m0 = blockIdx.y * BM;   // tb-tile
    const int n0 = blockIdx.x * BNT;  // feature-tile
    const int tid = threadIdx.x;
    const int tx = tid & 15;
    const int ty = tid >> 4;

    const int lr = tid >> 2;          // 0..63 row within tile (two passes)
    const int lc = tid & 3;           // float4 slot in K

    float acc[TM][TN];
    #pragma unroll
    for (int i = 0; i < TM; i++)
        #pragma unroll
        for (int j = 0; j < TN; j++) acc[i][j] = 0.f;

    for (int k0 = 0; k0 < N_; k0 += BK) {
        #pragma unroll
        for (int p = 0; p < 2; p++) {
            int row = lr + p * 64;
            float4 va = *(const float4*)&X[(size_t)(m0 + row) * N_ + k0 + lc * 4];
            As[lc*4+0][row] = va.x;
            As[lc*4+1][row] = va.y;
            As[lc*4+2][row] = va.z;
            As[lc*4+3][row] = va.w;
            float4 vb = *(const float4*)&W[(size_t)(n0 + row) * N_ + k0 + lc * 4];
            Bs[lc*4+0][row] = vb.x;
            Bs[lc*4+1][row] = vb.y;
            Bs[lc*4+2][row] = vb.z;
            Bs[lc*4+3][row] = vb.w;
        }
        __syncthreads();

        #pragma unroll
        for (int kk = 0; kk < BK; kk++) {
            float ra[TM], rb[TN];
            #pragma unroll
            for (int i = 0; i < TM; i++) ra[i] = As[kk][ty * TM + i];
            #pragma unroll
            for (int j = 0; j < TN; j++) rb[j] = Bs[kk][tx * TN + j];
            #pragma unroll
            for (int i = 0; i < TM; i++)
                #pragma unroll
                for (int j = 0; j < TN; j++)
                    acc[i][j] = fmaf(ra[i], rb[j], acc[i][j]);
        }
        __syncthreads();
    }

    #pragma unroll
    for (int i = 0; i < TM; i++) {
        size_t rowoff = (size_t)(m0 + ty * TM + i) * N_ + n0 + tx * TN;
        *(float4*)&H[rowoff + 0] = make_float4(acc[i][0], acc[i][1], acc[i][2], acc[i][3]);
        *(float4*)&H[rowoff + 4] = make_float4(acc[i][4], acc[i][5], acc[i][6], acc[i][7]);
    }
}

// ================= BN stats: stage 1 (partial column sums) =============
// grid: (N_/256, 32 row-chunks, 2 matrices), block 256
__global__ __launch_bounds__(256) void bn_partial_kernel()
{
    const int col = blockIdx.x * 256 + threadIdx.x;
    const int chunk = blockIdx.y;
    const float* __restrict__ H = blockIdx.z ? d_h2 : d_h1;
    const int r0 = chunk * 256;
    float s = 0.f, sq = 0.f;
    for (int r = 0; r < 256; r++) {
        float v = H[(size_t)(r0 + r) * N_ + col];
        s += v;
        sq = fmaf(v, v, sq);
    }
    int o = (blockIdx.z * 32 + chunk) * N_ + col;
    d_psum[o] = s;
    d_psq[o] = sq;
}

// ================= BN stats: stage 2 (finalize scale/bias) =============
// grid: (2*N_/256), block 256. Deterministic fixed-order reduction.
__global__ __launch_bounds__(256) void bn_final_kernel(
    const float* __restrict__ g1, const float* __restrict__ b1,
    const float* __restrict__ g2, const float* __restrict__ b2)
{
    const int idx = blockIdx.x * 256 + threadIdx.x;   // mat*N_ + col
    const int mat = idx >> 10;
    const int col = idx & (N_ - 1);
    float s = 0.f, sq = 0.f;
    for (int c = 0; c < 32; c++) {
        s  += d_psum[(mat * 32 + c) * N_ + col];
        sq += d_psq [(mat * 32 + c) * N_ + col];
    }
    const float inv = 1.f / (float)TB;
    float mean = s * inv;
    float var = sq * inv - mean * mean;
    float gamma = mat ? g2[col] : g1[col];
    float beta  = mat ? b2[col] : b1[col];
    float scale = gamma * rsqrtf(var + EPS);
    d_scale[idx] = scale;
    d_bias[idx] = beta - mean * scale;
}

// ============ Branch 1 (spatial): LIF over bn(h1), sum over N ==========
// grid: B_ blocks, 256 threads; each thread owns 4 features.
__global__ __launch_bounds__(256) void branch1_kernel()
{
    __shared__ int ssum[T_];
    const int b = blockIdx.x;
    const int tid = threadIdx.x;
    if (tid < T_) ssum[tid] = 0;
    __syncthreads();

    float v[4] = {0.f, 0.f, 0.f, 0.f};
    float sc[4], bi[4];
    #pragma unroll
    for (int j = 0; j < 4; j++) {
        sc[j] = d_scale[tid + j * 256];
        bi[j] = d_bias[tid + j * 256];
    }

    for (int t = 0; t < T_; t++) {
        const float* __restrict__ row = &d_h1[(size_t)(t * B_ + b) * N_];
        int cnt = 0;
        #pragma unroll
        for (int j = 0; j < 4; j++) {
            float h = fmaf(row[tid + j * 256], sc[j], bi[j]);
            v[j] = fmaf(v[j], 0.5f, h);
            bool s = (v[j] >= VTH);
            cnt += (int)s;
            if (s) v[j] = 0.f;
        }
        #pragma unroll
        for (int o = 16; o > 0; o >>= 1) cnt += __shfl_down_sync(0xffffffffu, cnt, o);
        if ((tid & 31) == 0) atomicAdd(&ssum[t], cnt);   // integer: exact, deterministic
    }
    __syncthreads();
    if (tid < T_) d_ssum[tid * B_ + b] = (float)ssum[tid];
}

// ============ Branch 2 (temporal): LIF over bn(h2), sum over T =========
// grid: BN_/256 blocks, 256 threads; thread = flat (b, m)
__global__ __launch_bounds__(256) void branch2_kernel()
{
    const int idx = blockIdx.x * 256 + threadIdx.x;
    const int m = idx & (N_ - 1);
    const float sc = d_scale[N_ + m];
    const float bi = d_bias[N_ + m];
    float v = 0.f;
    int cnt = 0;
    #pragma unroll 4
    for (int t = 0; t < T_; t++) {
        float h = fmaf(d_h2[(size_t)t * BN_ + idx], sc, bi);
        v = fmaf(v, 0.5f, h);
        if (v >= VTH) { cnt++; v = 0.f; }
    }
    d_tsum[idx] = (float)cnt;
}

// ============ Final: gate LIFs + output =================================
// out[t,b,n] = x + lif(x*ssum[t,b]) * lif(x*tsum[b,n])
__global__ __launch_bounds__(256) void final_kernel(
    const float* __restrict__ X, float* __restrict__ out)
{
    const int idx = blockIdx.x * 256 + threadIdx.x;  // b*N_ + n
    const int b = idx >> 10;
    __shared__ float ss[T_];
    if (threadIdx.x < T_) ss[threadIdx.x] = d_ssum[threadIdx.x * B_ + b];
    __syncthreads();

    const float ts = d_tsum[idx];
    float va = 0.f, vb = 0.f;
    #pragma unroll 4
    for (int t = 0; t < T_; t++) {
        float xt = X[(size_t)t * BN_ + idx];
        va = fmaf(va, 0.5f, xt * ss[t]);
        float a = 0.f;
        if (va >= VTH) { a = 1.f; va = 0.f; }
        vb = fmaf(vb, 0.5f, xt * ts);
        float bg = 0.f;
        if (vb >= VTH) { bg = 1.f; vb = 0.f; }
        out[(size_t)t * BN_ + idx] = xt + a * bg;
    }
}

// ======================================================================
extern "C" void kernel_launch(void* const* d_in, const int* in_sizes, int n_in,
                              void* d_out, int out_size)
{
    const float* x  = (const float*)d_in[0];
    const float* W1 = (const float*)d_in[1];
    const float* g1 = (const float*)d_in[2];
    const float* b1 = (const float*)d_in[3];
    const float* W2 = (const float*)d_in[4];
    const float* g2 = (const float*)d_in[5];
    const float* b2 = (const float*)d_in[6];
    float* out = (float*)d_out;

    // 1. Both GEMMs (grid.z selects W1/W2)
    dim3 ggrid(N_ / BNT, TB / BM, 2);
    gemm_kernel<<<ggrid, 256>>>(x, W1, W2);

    // 2. BatchNorm statistics (deterministic two-stage)
    dim3 pgrid(N_ / 256, 32, 2);
    bn_partial_kernel<<<pgrid, 256>>>();
    bn_final_kernel<<<(2 * N_) / 256, 256>>>(g1, b1, g2, b2);

    // 3. LIF branches -> spatial / temporal sums
    branch1_kernel<<<B_, 256>>>();
    branch2_kernel<<<BN_ / 256, 256>>>();

    // 4. Fused gate LIFs + output
    final_kernel<<<BN_ / 256, 256>>>(x, out);
}

// round 4
// speedup vs baseline: 1.4811x; 1.4811x over previous
#include <cuda_runtime.h>
#include <cstdint>

// Problem constants
#define T_  64
#define B_  128
#define N_  1024
#define TB  8192          // T_*B_
#define BN_ (B_*N_)       // 131072
#define VTH 1.0f
#define EPS 1e-5f

// -------- scratch (no allocation allowed -> __device__ globals) --------
__device__ float d_h1[TB * N_];            // 32 MB  linear1 output [tb, m]
__device__ float d_h2[TB * N_];            // 32 MB  linear2 output [tb, m]
__device__ float d_psum[2 * 32 * N_];      // BN stage-1 partial sums
__device__ float d_psq [2 * 32 * N_];      // BN stage-1 sum-of-squares
__device__ float d_scale[2 * N_];          // gamma * rsqrt(var+eps)
__device__ float d_bias [2 * N_];          // beta - mean*scale
__device__ int   d_ssum_i[T_ * B_];        // spatial spike counts (int, exact)
__device__ float d_tsum[B_ * N_];          // temporal_sum [b,m]

// ===================== mma.sync tf32 helpers ===========================
__device__ __forceinline__ uint32_t tf32_rn(float x) {
    uint32_t r; asm("cvt.rna.tf32.f32 %0, %1;" : "=r"(r) : "f"(x)); return r;
}
__device__ __forceinline__ void mma_tf32(float* d, const uint32_t* a, const uint32_t* b) {
    asm volatile(
        "mma.sync.aligned.m16n8k8.row.col.f32.tf32.tf32.f32 "
        "{%0,%1,%2,%3}, {%4,%5,%6,%7}, {%8,%9}, {%0,%1,%2,%3};"
        : "+f"(d[0]), "+f"(d[1]), "+f"(d[2]), "+f"(d[3])
        : "r"(a[0]), "r"(a[1]), "r"(a[2]), "r"(a[3]), "r"(b[0]), "r"(b[1]));
}

// ================= 3xTF32 GEMM: H = X @ W^T ===========================
// 128x128 CTA tile, 512 threads (16 warps on 32x32 warp tiles), K-chunk 32,
// double-buffered smem. hi = mask13(x) (exact tf32), lo = cvt(x - hi).
// acc += Ahi*Bhi + Ahi*Blo + Alo*Bhi  (fp32 accumulate in HMMA).
#define LDA 36
#define ASZ (128 * LDA)            // floats per operand tile
#define BUFSZ (2 * ASZ)            // A + B per stage
#define SMEM_BYTES (2 * BUFSZ * 4) // 73728

__global__ __launch_bounds__(512, 1) void gemm_tc(
    const float* __restrict__ X,
    const float* __restrict__ W1,
    const float* __restrict__ W2)
{
    extern __shared__ float sm[];
    const float* __restrict__ W = blockIdx.z ? W2 : W1;
    float* __restrict__ H = blockIdx.z ? d_h2 : d_h1;
    const int m0 = blockIdx.y * 128;
    const int n0 = blockIdx.x * 128;
    const int tid = threadIdx.x;
    const int lane = tid & 31, w = tid >> 5;
    const int wm = w & 3, wn = w >> 2;        // warp grid 4x4
    const int qr = lane >> 2, qc = lane & 3;  // quad row/col

    float acc[2][4][4];
    #pragma unroll
    for (int i = 0; i < 2; i++)
        #pragma unroll
        for (int j = 0; j < 4; j++)
            #pragma unroll
            for (int k = 0; k < 4; k++) acc[i][j][k] = 0.f;

    // loader mapping: 2 passes x (row, 4-float col) per operand
    const int lr = tid >> 3;
    const int lc = (tid & 7) * 4;

    float4 pa[2], pb[2];
    #pragma unroll
    for (int p = 0; p < 2; p++) {
        int row = lr + p * 64;
        pa[p] = *(const float4*)&X[(size_t)(m0 + row) * N_ + lc];
        pb[p] = *(const float4*)&W[(size_t)(n0 + row) * N_ + lc];
    }

    for (int c = 0; c < 32; c++) {
        float* SA = sm + (c & 1) * BUFSZ;
        float* SB = SA + ASZ;
        #pragma unroll
        for (int p = 0; p < 2; p++) {
            int row = lr + p * 64;
            *(float4*)&SA[row * LDA + lc] = pa[p];
            *(float4*)&SB[row * LDA + lc] = pb[p];
        }
        __syncthreads();
        if (c < 31) {
            const int k0 = (c + 1) * 32;
            #pragma unroll
            for (int p = 0; p < 2; p++) {
                int row = lr + p * 64;
                pa[p] = *(const float4*)&X[(size_t)(m0 + row) * N_ + k0 + lc];
                pb[p] = *(const float4*)&W[(size_t)(n0 + row) * N_ + k0 + lc];
            }
        }
        #pragma unroll
        for (int ks = 0; ks < 4; ks++) {
            const int kk = ks * 8;
            uint32_t aHi[2][4], aLo[2][4], bHi[4][2], bLo[4][2];
            #pragma unroll
            for (int mf = 0; mf < 2; mf++) {
                const int rb = wm * 32 + mf * 16;
                float va[4];
                va[0] = SA[(rb + qr)     * LDA + kk + qc];
                va[1] = SA[(rb + 8 + qr) * LDA + kk + qc];
                va[2] = SA[(rb + qr)     * LDA + kk + 4 + qc];
                va[3] = SA[(rb + 8 + qr) * LDA + kk + 4 + qc];
                #pragma unroll
                for (int j = 0; j < 4; j++) {
                    uint32_t h = __float_as_uint(va[j]) & 0xffffe000u;
                    aHi[mf][j] = h;
                    aLo[mf][j] = tf32_rn(va[j] - __uint_as_float(h));
                }
            }
            #pragma unroll
            for (int nf = 0; nf < 4; nf++) {
                const int cb = wn * 32 + nf * 8;
                float ub[2];
                ub[0] = SB[(cb + qr) * LDA + kk + qc];
                ub[1] = SB[(cb + qr) * LDA + kk + 4 + qc];
                #pragma unroll
                for (int j = 0; j < 2; j++) {
                    uint32_t h = __float_as_uint(ub[j]) & 0xffffe000u;
                    bHi[nf][j] = h;
                    bLo[nf][j] = tf32_rn(ub[j] - __uint_as_float(h));
                }
            }
            #pragma unroll
            for (int mf = 0; mf < 2; mf++)
                #pragma unroll
                for (int nf = 0; nf < 4; nf++) {
                    mma_tf32(acc[mf][nf], aHi[mf], bHi[nf]);
                    mma_tf32(acc[mf][nf], aHi[mf], bLo[nf]);
                    mma_tf32(acc[mf][nf], aLo[mf], bHi[nf]);
                }
        }
        __syncthreads();
    }

    // epilogue: write H tile from fragments
    #pragma unroll
    for (int mf = 0; mf < 2; mf++) {
        const int r = m0 + wm * 32 + mf * 16 + qr;
        #pragma unroll
        for (int nf = 0; nf < 4; nf++) {
            const int col = n0 + wn * 32 + nf * 8 + qc * 2;
            *(float2*)&H[(size_t)r * N_ + col] =
                make_float2(acc[mf][nf][0], acc[mf][nf][1]);
            *(float2*)&H[(size_t)(r + 8) * N_ + col] =
                make_float2(acc[mf][nf][2], acc[mf][nf][3]);
        }
    }
}

// ================= BN stats: stage 1 (partial column sums) =============
// grid: (N_/256, 32 row-chunks, 2 matrices), block 256. Deterministic.
__global__ __launch_bounds__(256) void bn_partial_kernel()
{
    const int col = blockIdx.x * 256 + threadIdx.x;
    const int chunk = blockIdx.y;
    const float* __restrict__ H = blockIdx.z ? d_h2 : d_h1;
    const int r0 = chunk * 256;
    float s = 0.f, sq = 0.f;
    for (int r = 0; r < 256; r++) {
        float v = H[(size_t)(r0 + r) * N_ + col];
        s += v;
        sq = fmaf(v, v, sq);
    }
    int o = (blockIdx.z * 32 + chunk) * N_ + col;
    d_psum[o] = s;
    d_psq[o] = sq;
}

// ================= BN finalize (+ zero spatial counters) ===============
__global__ __launch_bounds__(256) void bn_final_kernel(
    const float* __restrict__ g1, const float* __restrict__ b1,
    const float* __restrict__ g2, const float* __restrict__ b2)
{
    const int idx = blockIdx.x * 256 + threadIdx.x;   // mat*N_ + col
    const int mat = idx >> 10;
    const int col = idx & (N_ - 1);
    float s = 0.f, sq = 0.f;
    for (int c = 0; c < 32; c++) {
        s  += d_psum[(mat * 32 + c) * N_ + col];
        sq += d_psq [(mat * 32 + c) * N_ + col];
    }
    const float inv = 1.f / (float)TB;
    float mean = s * inv;
    float var = sq * inv - mean * mean;
    float gamma = mat ? g2[col] : g1[col];
    float beta  = mat ? b2[col] : b1[col];
    float scale = gamma * rsqrtf(var + EPS);
    d_scale[idx] = scale;
    d_bias[idx] = beta - mean * scale;
    // zero spatial spike counters (ordered before branch1 on the stream)
    #pragma unroll
    for (int j = 0; j < 4; j++) d_ssum_i[idx * 4 + j] = 0;
}

// ============ Branch 1 (spatial): LIF over bn(h1), sum over N ==========
// grid (B_, 4); block 256; one feature/thread; ballot+popc; int atomics.
__global__ __launch_bounds__(256) void branch1_kernel()
{
    __shared__ int ssum[T_];
    const int b = blockIdx.x;
    const int f = blockIdx.y * 256 + threadIdx.x;
    const int tid = threadIdx.x;
    const int lane = tid & 31;
    if (tid < T_) ssum[tid] = 0;
    __syncthreads();

    const float sc = d_scale[f];
    const float bi = d_bias[f];
    float v = 0.f;
    for (int t = 0; t < T_; t++) {
        float h = fmaf(d_h1[(size_t)(t * B_ + b) * N_ + f], sc, bi);
        v = fmaf(v, 0.5f, h);
        bool s = (v >= VTH);
        if (s) v = 0.f;
        unsigned bal = __ballot_sync(0xffffffffu, s);
        if (lane == 0) atomicAdd(&ssum[t], __popc(bal));
    }
    __syncthreads();
    if (tid < T_) atomicAdd(&d_ssum_i[tid * B_ + b], ssum[tid]);
}

// ============ Branch 2 (temporal): LIF over bn(h2), sum over T =========
__global__ __launch_bounds__(256) void branch2_kernel()
{
    const int idx = blockIdx.x * 256 + threadIdx.x;
    const int m = idx & (N_ - 1);
    const float sc = d_scale[N_ + m];
    const float bi = d_bias[N_ + m];
    float v = 0.f;
    int cnt = 0;
    #pragma unroll 4
    for (int t = 0; t < T_; t++) {
        float h = fmaf(d_h2[(size_t)t * BN_ + idx], sc, bi);
        v = fmaf(v, 0.5f, h);
        if (v >= VTH) { cnt++; v = 0.f; }
    }
    d_tsum[idx] = (float)cnt;
}

// ============ Final: gate LIFs + output =================================
__global__ __launch_bounds__(256) void final_kernel(
    const float* __restrict__ X, float* __restrict__ out)
{
    const int idx = blockIdx.x * 256 + threadIdx.x;  // b*N_ + n
    const int b = idx >> 10;
    __shared__ float ss[T_];
    if (threadIdx.x < T_) ss[threadIdx.x] = (float)d_ssum_i[threadIdx.x * B_ + b];
    __syncthreads();

    const float ts = d_tsum[idx];
    float va = 0.f, vb = 0.f;
    #pragma unroll 4
    for (int t = 0; t < T_; t++) {
        float xt = X[(size_t)t * BN_ + idx];
        va = fmaf(va, 0.5f, xt * ss[t]);
        float a = 0.f;
        if (va >= VTH) { a = 1.f; va = 0.f; }
        vb = fmaf(vb, 0.5f, xt * ts);
        float bg = 0.f;
        if (vb >= VTH) { bg = 1.f; vb = 0.f; }
        out[(size_t)t * BN_ + idx] = xt + a * bg;
    }
}

// ======================================================================
extern "C" void kernel_launch(void* const* d_in, const int* in_sizes, int n_in,
                              void* d_out, int out_size)
{
    const float* x  = (const float*)d_in[0];
    const float* W1 = (const float*)d_in[1];
    const float* g1 = (const float*)d_in[2];
    const float* b1 = (const float*)d_in[3];
    const float* W2 = (const float*)d_in[4];
    const float* g2 = (const float*)d_in[5];
    const float* b2 = (const float*)d_in[6];
    float* out = (float*)d_out;

    cudaFuncSetAttribute(gemm_tc, cudaFuncAttributeMaxDynamicSharedMemorySize, SMEM_BYTES);

    // 1. Both GEMMs on tensor cores via mma.sync 3xTF32
    dim3 ggrid(N_ / 128, TB / 128, 2);
    gemm_tc<<<ggrid, 512, SMEM_BYTES>>>(x, W1, W2);

    // 2. BatchNorm statistics (deterministic two-stage) + zero counters
    dim3 pgrid(N_ / 256, 32, 2);
    bn_partial_kernel<<<pgrid, 256>>>();
    bn_final_kernel<<<(2 * N_) / 256, 256>>>(g1, b1, g2, b2);

    // 3. LIF branches
    dim3 b1grid(B_, 4);
    branch1_kernel<<<b1grid, 256>>>();
    branch2_kernel<<<BN_ / 256, 256>>>();

    // 4. Fused gate LIFs + output
    final_kernel<<<BN_ / 256, 256>>>(x, out);
}